// round 2
// baseline (speedup 1.0000x reference)
#include <cuda_runtime.h>
#include <math.h>

#define BB 16
#define AA 3
#define HH 80
#define WW 80
#define NC 80
#define CH 85
#define MGT 32
#define NCELL (BB*AA*HH*WW)          // 307200
#define CELLS_PER_B (AA*HH*WW)       // 19200
#define EPSF 1e-8f
#define INPUT_SIZE 640.0f
#define IGN_IOU 0.5f

// ---- device scratch (no allocations allowed) ----
__device__ float  g_gt[BB * MGT * 4];   // per-batch GT boxes (xyxy)
__device__ int    g_cnt[BB];
__device__ double g_acc[6];             // npos, giou_sum, pos_obj, neg_obj, nneg, cls_sum

__device__ __forceinline__ float softplusf(float x) {
    return fmaxf(x, 0.0f) + log1pf(expf(-fabsf(x)));
}

__device__ __forceinline__ float warp_sum(float v) {
    #pragma unroll
    for (int o = 16; o > 0; o >>= 1) v += __shfl_xor_sync(0xffffffffu, v, o);
    return v;
}

// Compute xyxy box from (tx_or_sig, ty_or_sig, tw, th) given grid pos + anchor.
__device__ __forceinline__ void make_box(float cx_in, float cy_in, float tw, float th,
                                         float aw, float ah,
                                         float& x1, float& y1, float& x2, float& y2) {
    float cx = cx_in * (1.0f / (float)WW);
    float cy = cy_in * (1.0f / (float)HH);
    float bw = aw * expf(tw) * (1.0f / INPUT_SIZE);
    float bh = ah * expf(th) * (1.0f / INPUT_SIZE);
    x1 = cx - 0.5f * bw; y1 = cy - 0.5f * bh;
    x2 = cx + 0.5f * bw; y2 = cy + 0.5f * bh;
}

__global__ void k_init() {
    int t = threadIdx.x;
    if (t < 6)  g_acc[t] = 0.0;
    if (t < BB) g_cnt[t] = 0;
}

// Gather ground-truth boxes per batch (cells where t_obj > 0).
__global__ void k_gather(const float* __restrict__ targets) {
    int idx = blockIdx.x * blockDim.x + threadIdx.x;
    if (idx >= NCELL) return;
    const float* t = targets + (size_t)idx * CH;
    float tobj = t[4];
    if (tobj > 0.0f) {
        int b  = idx / CELLS_PER_B;
        int r  = idx % CELLS_PER_B;
        int a  = r / (HH * WW);
        int hw = r % (HH * WW);
        int hy = hw / WW;
        int wx = hw % WW;
        const float AWv[3] = {10.0f, 16.0f, 33.0f};
        const float AHv[3] = {13.0f, 30.0f, 23.0f};
        float x1, y1, x2, y2;
        make_box(t[0] + (float)wx, t[1] + (float)hy, t[2], t[3], AWv[a], AHv[a],
                 x1, y1, x2, y2);
        int slot = atomicAdd(&g_cnt[b], 1);
        if (slot < MGT) {
            float* g = g_gt + ((size_t)b * MGT + slot) * 4;
            g[0] = x1; g[1] = y1; g[2] = x2; g[3] = y2;
        }
    }
}

__global__ void __launch_bounds__(256) k_main(const float* __restrict__ preds,
                                              const float* __restrict__ targets) {
    __shared__ float s_gt[MGT * 4];
    __shared__ int   s_cnt;
    __shared__ float s_red[6][8];

    int idx = blockIdx.x * 256 + threadIdx.x;
    int b   = idx / CELLS_PER_B;     // 256 | 19200 -> whole block in one batch

    if (threadIdx.x < MGT * 4) s_gt[threadIdx.x] = g_gt[b * MGT * 4 + threadIdx.x];
    if (threadIdx.x == 0)      s_cnt = min(g_cnt[b], MGT);
    __syncthreads();

    int r  = idx % CELLS_PER_B;
    int a  = r / (HH * WW);
    int hw = r % (HH * WW);
    int hy = hw / WW;
    int wx = hw % WW;

    const float AWv[3] = {10.0f, 16.0f, 33.0f};
    const float AHv[3] = {13.0f, 30.0f, 23.0f};
    float aw = AWv[a], ah = AHv[a];

    const float* p = preds   + (size_t)idx * CH;
    const float* t = targets + (size_t)idx * CH;

    float ptx = p[0], pty = p[1], ptw = p[2], pth = p[3], pobj = p[4];
    float ttx = t[0], tty = t[1], ttw = t[2], tth = t[3], tobj = t[4];

    // pred box (sigmoid on xy)
    float sx = 1.0f / (1.0f + expf(-ptx));
    float sy = 1.0f / (1.0f + expf(-pty));
    float px1, py1, px2, py2;
    make_box(sx + (float)wx, sy + (float)hy, ptw, pth, aw, ah, px1, py1, px2, py2);
    // target box
    float tx1, ty1, tx2, ty2;
    make_box(ttx + (float)wx, tty + (float)hy, ttw, tth, aw, ah, tx1, ty1, tx2, ty2);

    float areaP = (px2 - px1) * (py2 - py1);

    // max IoU vs this batch's GT boxes
    float best = -1.0f;
    int cnt = s_cnt;
    #pragma unroll 8
    for (int i = 0; i < cnt; i++) {
        float gx1 = s_gt[i * 4 + 0], gy1 = s_gt[i * 4 + 1];
        float gx2 = s_gt[i * 4 + 2], gy2 = s_gt[i * 4 + 3];
        float areaG = (gx2 - gx1) * (gy2 - gy1);
        float iw = fminf(px2, gx2) - fmaxf(px1, gx1);
        float ih = fminf(py2, gy2) - fmaxf(py1, gy1);
        iw = fmaxf(iw, 0.0f); ih = fmaxf(ih, 0.0f);
        float inter = iw * ih;
        float iou = inter / (areaP + areaG - inter + EPSF);
        best = fmaxf(best, iou);
    }

    bool pos = tobj > 0.0f;
    bool ign = best > IGN_IOU;
    float posf = pos ? 1.0f : 0.0f;
    float negf = (!pos && !ign) ? 1.0f : 0.0f;

    // GIoU loss (pred vs target box)
    float areaT = (tx2 - tx1) * (ty2 - ty1);
    float iw = fmaxf(fminf(px2, tx2) - fmaxf(px1, tx1), 0.0f);
    float ih = fmaxf(fminf(py2, ty2) - fmaxf(py1, ty1), 0.0f);
    float inter = iw * ih;
    float uni  = areaP + areaT - inter;
    float iou  = inter / (uni + EPSF);
    float cw = fmaxf(fmaxf(px2, tx2) - fminf(px1, tx1), 0.0f);
    float chh = fmaxf(fmaxf(py2, ty2) - fminf(py1, ty1), 0.0f);
    float areaC = cw * chh;
    float giou = iou - (areaC - uni) / (areaC + EPSF);
    float giou_l = 1.0f - giou;

    // obj BCE
    float obj_l = softplusf(pobj) - pobj * tobj;

    // cls BCE — only read the 80 channels for positive cells (512 of 307200)
    float cls_sum = 0.0f;
    if (pos) {
        #pragma unroll 4
        for (int c = 0; c < NC; c++) {
            float x = p[5 + c];
            float tc = t[5 + c];
            cls_sum += softplusf(x) - x * tc;
        }
    }

    float vals[6];
    vals[0] = posf;
    vals[1] = giou_l * posf;
    vals[2] = obj_l * posf;
    vals[3] = obj_l * negf;
    vals[4] = negf;
    vals[5] = cls_sum;

    int lane = threadIdx.x & 31;
    int wid  = threadIdx.x >> 5;
    #pragma unroll
    for (int k = 0; k < 6; k++) {
        float v = warp_sum(vals[k]);
        if (lane == 0) s_red[k][wid] = v;
    }
    __syncthreads();
    if (wid == 0) {
        #pragma unroll
        for (int k = 0; k < 6; k++) {
            float v = (lane < 8) ? s_red[k][lane] : 0.0f;
            v = warp_sum(v);
            if (lane == 0) atomicAdd(&g_acc[k], (double)v);
        }
    }
}

__global__ void k_final(float* __restrict__ out) {
    if (threadIdx.x != 0 || blockIdx.x != 0) return;
    double npos = g_acc[0], gsum = g_acc[1], pobj = g_acc[2];
    double nobj = g_acc[3], nneg = g_acc[4], csum = g_acc[5];
    float giou_v = (float)(gsum / (npos + (double)EPSF));
    float obj_v  = (float)((5.0 * pobj + nobj) / (5.0 * npos + nneg + (double)EPSF));
    float cls_v  = (float)(csum / (npos + (double)EPSF));
    out[0] = giou_v + obj_v + cls_v;
    out[1] = giou_v;
    out[2] = obj_v;
    out[3] = cls_v;
}

extern "C" void kernel_launch(void* const* d_in, const int* in_sizes, int n_in,
                              void* d_out, int out_size) {
    const float* preds   = (const float*)d_in[0];
    const float* targets = (const float*)d_in[1];
    float* out = (float*)d_out;

    k_init<<<1, 32>>>();
    k_gather<<<(NCELL + 255) / 256, 256>>>(targets);
    k_main<<<NCELL / 256, 256>>>(preds, targets);
    k_final<<<1, 32>>>(out);
}